// round 6
// baseline (speedup 1.0000x reference)
#include <cuda_runtime.h>

// ---------------- problem constants ----------------
#define BB   256
#define CC   3
#define HH   224
#define WWD  224
#define RET  32
#define GDIM 9216          // 3 * 3 * 32 * 32
#define HGN  1024
#define HLN  256
#define HOUT 1280          // HG + HL

#define S1   8             // split-K for GEMM1 (K=9216 -> 1152/split)
#define S2   4             // split-K for out GEMM (K=1024 -> 256/split)
#define S3   2             // split-K for hl GEMM  (K=256  -> 128/split)

// ---------------- scratch (device globals; no allocation allowed) ----------
__device__ float g_buf [BB * GDIM];          // foveated glimpse (B, 9216)
__device__ float h1_buf[BB * HGN];           // relu(g@W1+b1)
__device__ float h2_buf[BB * HLN];           // relu(loc@W2+b2)
__device__ float part1[S1 * BB * HGN];       // GEMM1 partials
__device__ float part2[S2 * BB * HOUT];      // h1@W3 partials
__device__ float part3[S3 * BB * HOUT];      // h2@W4 partials

// ---------------- packed fp32x2 helpers (sm_103a FFMA2) --------------------
__device__ __forceinline__ void fma2(unsigned long long& d,
                                     unsigned long long a,
                                     unsigned long long b) {
    asm("fma.rn.f32x2 %0, %1, %2, %0;" : "+l"(d) : "l"(a), "l"(b));
}
__device__ __forceinline__ unsigned long long pack_dup(float x) {
    unsigned long long r;
    unsigned xi = __float_as_uint(x);
    asm("mov.b64 %0, {%1, %2};" : "=l"(r) : "r"(xi), "r"(xi));
    return r;
}
__device__ __forceinline__ float2 unpack2(unsigned long long v) {
    unsigned lo, hi;
    asm("mov.b64 {%0, %1}, %2;" : "=r"(lo), "=r"(hi) : "l"(v));
    return make_float2(__uint_as_float(lo), __uint_as_float(hi));
}

// ---------------- foveation -----------------------------------------------
__global__ void foveate_kernel(const float* __restrict__ img,
                               const float* __restrict__ loc) {
    int idx = blockIdx.x * blockDim.x + threadIdx.x;
    if (idx >= BB * GDIM) return;
    int b  = idx / GDIM;
    int r  = idx - b * GDIM;
    int z  = r / (CC * RET * RET);
    int r2 = r - z * (CC * RET * RET);
    int c  = r2 / (RET * RET);
    int p  = r2 - c * (RET * RET);
    int y  = p >> 5;
    int x  = p & 31;

    float dr = (loc[b * 2 + 0] + 1.0f) * 0.5f * (float)WWD;
    float dc = (loc[b * 2 + 1] + 1.0f) * 0.5f * (float)WWD;
    int half = 16 << z;
    int top  = (int)(dr - (float)half);
    int left = (int)(dc - (float)half);

    const float* im = img + ((size_t)b * CC + c) * (HH * WWD);
    float v;
    if (z == 0) {
        v = im[(top + y) * WWD + (left + x)];
    } else {
        int off = (z == 2) ? 1 : 0;
        int yy = top  + (y << z) + off;
        int xx = left + (x << z) + off;
        const float* p0 = im + yy * WWD + xx;
        v = 0.25f * (p0[0] + p0[1] + p0[WWD] + p0[WWD + 1]);
    }
    g_buf[idx] = v;
}

// ---------------- location FC (K=2) ---------------------------------------
__global__ void loc_fc_kernel(const float* __restrict__ loc,
                              const float* __restrict__ W2,
                              const float* __restrict__ b2) {
    int b = blockIdx.x;
    int n = threadIdx.x;
    float l0 = loc[b * 2 + 0];
    float l1 = loc[b * 2 + 1];
    float v = fmaf(l0, W2[n], fmaf(l1, W2[HLN + n], b2[n]));
    h2_buf[b * HLN + n] = fmaxf(v, 0.0f);
}

// ---------------- split-K fp32 GEMM, 8x8 micro-tile, FFMA2 -----------------
// part[z][M][N] = A[M x Kc chunk z] @ W[chunk z x N]
// BM=64, BN=128, BK=32, 128 threads.
// Thread (ty=tid>>4 in 0..7, tx=tid&15 in 0..15) owns rows ty*8..+7, cols tx*8..+7.
// Accumulators packed over M pairs: acc[mp][n] = (row 2mp, row 2mp+1) x col n.
__global__ __launch_bounds__(128)
void gemm_splitk_kernel(const float* __restrict__ A, const float* __restrict__ W,
                        float* __restrict__ part, int M, int N, int K, int Kc) {
    __shared__ float As[32][68];    // [k][m], stride 68 floats (16B-aligned rows)
    __shared__ float Ws[32][128];   // [k][n]

    const int tid = threadIdx.x;
    const int bm  = blockIdx.y;
    const int bn  = blockIdx.x;
    const int sz  = blockIdx.z;
    const int ty  = tid >> 4;       // 0..7
    const int tx  = tid & 15;       // 0..15

    const int kbase = sz * Kc;

    unsigned long long acc[4][8];
    #pragma unroll
    for (int i = 0; i < 4; i++)
        #pragma unroll
        for (int j = 0; j < 8; j++) acc[i][j] = 0ull;

    for (int k0 = 0; k0 < Kc; k0 += 32) {
        // A tile (64 m x 32 k): 512 float4, 4/thread, coalesced; store transposed
        #pragma unroll
        for (int t = 0; t < 4; t++) {
            int i  = t * 128 + tid;
            int ar = i >> 3;              // 0..63  (m)
            int ac = (i & 7) << 2;        // 0..28  (k)
            float4 v = *(const float4*)(A + (size_t)(bm * 64 + ar) * K + kbase + k0 + ac);
            As[ac + 0][ar] = v.x;
            As[ac + 1][ar] = v.y;
            As[ac + 2][ar] = v.z;
            As[ac + 3][ar] = v.w;
        }
        // W tile (32 k x 128 n): 1024 float4, 8/thread, coalesced
        #pragma unroll
        for (int t = 0; t < 8; t++) {
            int i  = t * 128 + tid;
            int wr = i >> 5;              // 0..31 (k)
            int wc = (i & 31) << 2;       // 0..124 (n)
            *(float4*)(&Ws[wr][wc]) =
                *(const float4*)(W + (size_t)(kbase + k0 + wr) * N + bn * 128 + wc);
        }
        __syncthreads();

        #pragma unroll 8
        for (int kk = 0; kk < 32; kk++) {
            // A: 8 consecutive m-values -> 4 natural u64 pairs (16B aligned)
            const ulonglong2* ap = (const ulonglong2*)(&As[kk][ty * 8]);
            ulonglong2 a01 = ap[0];
            ulonglong2 a23 = ap[1];
            // W: 8 n-values, duplicate-pack each
            float4 w0 = *(const float4*)(&Ws[kk][tx * 8]);
            float4 w1 = *(const float4*)(&Ws[kk][tx * 8 + 4]);
            unsigned long long wd0 = pack_dup(w0.x);
            unsigned long long wd1 = pack_dup(w0.y);
            unsigned long long wd2 = pack_dup(w0.z);
            unsigned long long wd3 = pack_dup(w0.w);
            unsigned long long wd4 = pack_dup(w1.x);
            unsigned long long wd5 = pack_dup(w1.y);
            unsigned long long wd6 = pack_dup(w1.z);
            unsigned long long wd7 = pack_dup(w1.w);

            fma2(acc[0][0], a01.x, wd0); fma2(acc[0][1], a01.x, wd1);
            fma2(acc[0][2], a01.x, wd2); fma2(acc[0][3], a01.x, wd3);
            fma2(acc[0][4], a01.x, wd4); fma2(acc[0][5], a01.x, wd5);
            fma2(acc[0][6], a01.x, wd6); fma2(acc[0][7], a01.x, wd7);

            fma2(acc[1][0], a01.y, wd0); fma2(acc[1][1], a01.y, wd1);
            fma2(acc[1][2], a01.y, wd2); fma2(acc[1][3], a01.y, wd3);
            fma2(acc[1][4], a01.y, wd4); fma2(acc[1][5], a01.y, wd5);
            fma2(acc[1][6], a01.y, wd6); fma2(acc[1][7], a01.y, wd7);

            fma2(acc[2][0], a23.x, wd0); fma2(acc[2][1], a23.x, wd1);
            fma2(acc[2][2], a23.x, wd2); fma2(acc[2][3], a23.x, wd3);
            fma2(acc[2][4], a23.x, wd4); fma2(acc[2][5], a23.x, wd5);
            fma2(acc[2][6], a23.x, wd6); fma2(acc[2][7], a23.x, wd7);

            fma2(acc[3][0], a23.y, wd0); fma2(acc[3][1], a23.y, wd1);
            fma2(acc[3][2], a23.y, wd2); fma2(acc[3][3], a23.y, wd3);
            fma2(acc[3][4], a23.y, wd4); fma2(acc[3][5], a23.y, wd5);
            fma2(acc[3][6], a23.y, wd6); fma2(acc[3][7], a23.y, wd7);
        }
        __syncthreads();
    }

    // write raw partials: part[sz][row][col]
    float* pout = part + (size_t)sz * M * N;
    const int col0 = bn * 128 + tx * 8;
    #pragma unroll
    for (int mp = 0; mp < 4; mp++) {
        int row0 = bm * 64 + ty * 8 + mp * 2;
        float r0[8], r1[8];
        #pragma unroll
        for (int n = 0; n < 8; n++) {
            float2 p = unpack2(acc[mp][n]);
            r0[n] = p.x;
            r1[n] = p.y;
        }
        *(float4*)(pout + (size_t)row0 * N + col0)           = make_float4(r0[0], r0[1], r0[2], r0[3]);
        *(float4*)(pout + (size_t)row0 * N + col0 + 4)       = make_float4(r0[4], r0[5], r0[6], r0[7]);
        *(float4*)(pout + (size_t)(row0 + 1) * N + col0)     = make_float4(r1[0], r1[1], r1[2], r1[3]);
        *(float4*)(pout + (size_t)(row0 + 1) * N + col0 + 4) = make_float4(r1[4], r1[5], r1[6], r1[7]);
    }
}

// ---------------- reduce 1: h1 = relu(sum_s part1 + b1) --------------------
__global__ void reduce1_kernel(const float* __restrict__ b1) {
    int idx4 = blockIdx.x * blockDim.x + threadIdx.x;        // over (BB*HGN)/4
    if (idx4 >= BB * HGN / 4) return;
    int idx = idx4 * 4;
    int n   = idx % HGN;
    float4 s = *(const float4*)(part1 + idx);
    #pragma unroll
    for (int z = 1; z < S1; z++) {
        float4 v = *(const float4*)(part1 + (size_t)z * BB * HGN + idx);
        s.x += v.x; s.y += v.y; s.z += v.z; s.w += v.w;
    }
    float4 bv = *(const float4*)(b1 + n);
    s.x = fmaxf(s.x + bv.x, 0.0f);
    s.y = fmaxf(s.y + bv.y, 0.0f);
    s.z = fmaxf(s.z + bv.z, 0.0f);
    s.w = fmaxf(s.w + bv.w, 0.0f);
    *(float4*)(h1_buf + idx) = s;
}

// ---------------- final reduce: out = relu(Σpart2+b3) + relu(Σpart3+b4) ----
__global__ void final_reduce_kernel(const float* __restrict__ b3,
                                    const float* __restrict__ b4,
                                    float* __restrict__ out) {
    int idx4 = blockIdx.x * blockDim.x + threadIdx.x;        // over (BB*HOUT)/4
    if (idx4 >= BB * HOUT / 4) return;
    int idx = idx4 * 4;
    int n   = idx % HOUT;

    float4 sg = *(const float4*)(part2 + idx);
    #pragma unroll
    for (int z = 1; z < S2; z++) {
        float4 v = *(const float4*)(part2 + (size_t)z * BB * HOUT + idx);
        sg.x += v.x; sg.y += v.y; sg.z += v.z; sg.w += v.w;
    }
    float4 sl = *(const float4*)(part3 + idx);
    #pragma unroll
    for (int z = 1; z < S3; z++) {
        float4 v = *(const float4*)(part3 + (size_t)z * BB * HOUT + idx);
        sl.x += v.x; sl.y += v.y; sl.z += v.z; sl.w += v.w;
    }
    float4 g3 = *(const float4*)(b3 + n);
    float4 g4 = *(const float4*)(b4 + n);
    float4 o;
    o.x = fmaxf(sg.x + g3.x, 0.0f) + fmaxf(sl.x + g4.x, 0.0f);
    o.y = fmaxf(sg.y + g3.y, 0.0f) + fmaxf(sl.y + g4.y, 0.0f);
    o.z = fmaxf(sg.z + g3.z, 0.0f) + fmaxf(sl.z + g4.z, 0.0f);
    o.w = fmaxf(sg.w + g3.w, 0.0f) + fmaxf(sl.w + g4.w, 0.0f);
    *(float4*)(out + idx) = o;        // relu(hg+hl) == relu(hg)+relu(hl)
}

// ---------------- launch ----------------------------------------------------
extern "C" void kernel_launch(void* const* d_in, const int* in_sizes, int n_in,
                              void* d_out, int out_size) {
    const float* images    = (const float*)d_in[0];
    const float* locations = (const float*)d_in[1];
    const float* W1        = (const float*)d_in[2];
    const float* b1        = (const float*)d_in[3];
    const float* W2        = (const float*)d_in[4];
    const float* b2        = (const float*)d_in[5];
    const float* W3        = (const float*)d_in[6];
    const float* b3        = (const float*)d_in[7];
    const float* W4        = (const float*)d_in[8];
    const float* b4        = (const float*)d_in[9];
    float* out = (float*)d_out;
    (void)in_sizes; (void)n_in; (void)out_size;

    void *gp, *h1p, *h2p, *p1p, *p2p, *p3p;
    cudaGetSymbolAddress(&gp,  g_buf);
    cudaGetSymbolAddress(&h1p, h1_buf);
    cudaGetSymbolAddress(&h2p, h2_buf);
    cudaGetSymbolAddress(&p1p, part1);
    cudaGetSymbolAddress(&p2p, part2);
    cudaGetSymbolAddress(&p3p, part3);

    // 1) foveation -> g_buf
    foveate_kernel<<<(BB * GDIM + 255) / 256, 256>>>(images, locations);

    // 2) location FC -> h2_buf
    loc_fc_kernel<<<BB, HLN>>>(locations, W2, b2);

    // 3) hl partials: h2 @ W4   (256 x 1280, K=256, S=2) -> part3
    gemm_splitk_kernel<<<dim3(HOUT / 128, BB / 64, S3), 128>>>(
        (const float*)h2p, W4, (float*)p3p, BB, HOUT, HLN, HLN / S3);

    // 4) GEMM1 partials: g @ W1 (256 x 1024, K=9216, S=8) -> part1
    gemm_splitk_kernel<<<dim3(HGN / 128, BB / 64, S1), 128>>>(
        (const float*)gp, W1, (float*)p1p, BB, HGN, GDIM, GDIM / S1);

    // 5) h1 = relu(sum part1 + b1)
    reduce1_kernel<<<(BB * HGN / 4 + 255) / 256, 256>>>(b1);

    // 6) out partials: h1 @ W3  (256 x 1280, K=1024, S=4) -> part2
    gemm_splitk_kernel<<<dim3(HOUT / 128, BB / 64, S2), 128>>>(
        (const float*)h1p, W3, (float*)p2p, BB, HOUT, HGN, HGN / S2);

    // 7) out = relu(sum part2 + b3) + relu(sum part3 + b4)
    final_reduce_kernel<<<(BB * HOUT / 4 + 255) / 256, 256>>>(b3, b4, out);
}

// round 7
// speedup vs baseline: 1.2869x; 1.2869x over previous
#include <cuda_runtime.h>
#include <cstdint>

// ---------------- problem constants ----------------
#define BB   256
#define CC   3
#define HH   224
#define WWD  224
#define RET  32
#define GDIM 9216          // 3 * 3 * 32 * 32
#define HGN  1024
#define HLN  256
#define HOUT 1280          // HG + HL

#define S1   16            // split-K for GEMM1 (K=9216 -> 576/split)
#define S2   8             // split-K for out GEMM (K=1024 -> 128/split)
#define S3   2             // split-K for hl GEMM  (K=256  -> 128/split)

#define BM   64
#define BN   128
#define BK   32

// ---------------- scratch (device globals; no allocation allowed) ----------
__device__ float g_buf [BB * GDIM];          // foveated glimpse (B, 9216)
__device__ float h1_buf[BB * HGN];           // relu(g@W1+b1)
__device__ float h2_buf[BB * HLN];           // relu(loc@W2+b2)
__device__ float part1[S1 * BB * HGN];       // GEMM1 partials (16 MB)
__device__ float part2[S2 * BB * HOUT];      // h1@W3 partials
__device__ float part3[S3 * BB * HOUT];      // h2@W4 partials

// ---------------- packed fp32x2 helpers (sm_103a FFMA2) --------------------
__device__ __forceinline__ void fma2(unsigned long long& d,
                                     unsigned long long a,
                                     unsigned long long b) {
    asm("fma.rn.f32x2 %0, %1, %2, %0;" : "+l"(d) : "l"(a), "l"(b));
}
__device__ __forceinline__ unsigned long long pack_dup(float x) {
    unsigned long long r;
    unsigned xi = __float_as_uint(x);
    asm("mov.b64 %0, {%1, %2};" : "=l"(r) : "r"(xi), "r"(xi));
    return r;
}
__device__ __forceinline__ float2 unpack2(unsigned long long v) {
    unsigned lo, hi;
    asm("mov.b64 {%0, %1}, %2;" : "=r"(lo), "=r"(hi) : "l"(v));
    return make_float2(__uint_as_float(lo), __uint_as_float(hi));
}

// ---------------- cp.async helpers -----------------------------------------
__device__ __forceinline__ void cp16(uint32_t smem_dst, const void* gsrc) {
    asm volatile("cp.async.cg.shared.global [%0], [%1], 16;"
                 :: "r"(smem_dst), "l"(gsrc) : "memory");
}
__device__ __forceinline__ void cp_commit() {
    asm volatile("cp.async.commit_group;" ::: "memory");
}
template<int NG>
__device__ __forceinline__ void cp_wait() {
    asm volatile("cp.async.wait_group %0;" :: "n"(NG) : "memory");
}

// ---------------- foveation -----------------------------------------------
__global__ void foveate_kernel(const float* __restrict__ img,
                               const float* __restrict__ loc) {
    int idx = blockIdx.x * blockDim.x + threadIdx.x;
    if (idx >= BB * GDIM) return;
    int b  = idx / GDIM;
    int r  = idx - b * GDIM;
    int z  = r / (CC * RET * RET);
    int r2 = r - z * (CC * RET * RET);
    int c  = r2 / (RET * RET);
    int p  = r2 - c * (RET * RET);
    int y  = p >> 5;
    int x  = p & 31;

    float dr = (loc[b * 2 + 0] + 1.0f) * 0.5f * (float)WWD;
    float dc = (loc[b * 2 + 1] + 1.0f) * 0.5f * (float)WWD;
    int half = 16 << z;
    int top  = (int)(dr - (float)half);
    int left = (int)(dc - (float)half);

    const float* im = img + ((size_t)b * CC + c) * (HH * WWD);
    float v;
    if (z == 0) {
        v = im[(top + y) * WWD + (left + x)];
    } else {
        int off = (z == 2) ? 1 : 0;
        int yy = top  + (y << z) + off;
        int xx = left + (x << z) + off;
        const float* p0 = im + yy * WWD + xx;
        v = 0.25f * (p0[0] + p0[1] + p0[WWD] + p0[WWD + 1]);
    }
    g_buf[idx] = v;
}

// ---------------- location FC (K=2) ---------------------------------------
__global__ void loc_fc_kernel(const float* __restrict__ loc,
                              const float* __restrict__ W2,
                              const float* __restrict__ b2) {
    int b = blockIdx.x;
    int n = threadIdx.x;
    float l0 = loc[b * 2 + 0];
    float l1 = loc[b * 2 + 1];
    float v = fmaf(l0, W2[n], fmaf(l1, W2[HLN + n], b2[n]));
    h2_buf[b * HLN + n] = fmaxf(v, 0.0f);
}

// ---------------- split-K fp32 GEMM, cp.async double-buffered --------------
// part[z][M][N] = A[M x Kc chunk z] @ W[chunk z x N]
// BM=64, BN=128, BK=32, 128 threads, 8x8 per-thread tile, FFMA2.
// A kept row-major [m][k] in smem (cp.async direct); accumulators packed
// over N pairs (W rows give natural u64 pairs).
__global__ __launch_bounds__(128)
void gemm_splitk_kernel(const float* __restrict__ A, const float* __restrict__ W,
                        float* __restrict__ part, int M, int N, int K, int Kc) {
    __shared__ float As[2][BM][BK];    // 2 x 8 KB
    __shared__ float Ws[2][BK][BN];    // 2 x 16 KB   (total 48 KB)

    const int tid = threadIdx.x;
    const int bm  = blockIdx.y;
    const int bn  = blockIdx.x;
    const int sz  = blockIdx.z;
    const int ty  = tid >> 4;       // 0..7  -> rows ty*8..+7
    const int tx  = tid & 15;       // 0..15 -> cols tx*8..+7

    const int kbase = sz * Kc;
    const int T     = Kc / BK;

    const uint32_t as_base = (uint32_t)__cvta_generic_to_shared(&As[0][0][0]);
    const uint32_t ws_base = (uint32_t)__cvta_generic_to_shared(&Ws[0][0][0]);

    // async load of tile `it` into buffer `b`
    auto load_tiles = [&](int it, int b) {
        const int k0 = kbase + it * BK;
        // A: 64 rows x 32 k = 512 16B-chunks, 4/thread, coalesced
        const float* Ag = A + (size_t)(bm * BM) * K + k0;
        #pragma unroll
        for (int t = 0; t < 4; t++) {
            int id = t * 128 + tid;
            int m  = id >> 3;
            int c  = (id & 7) << 2;
            cp16(as_base + (uint32_t)(((b * BM + m) * BK + c) * 4),
                 Ag + (size_t)m * K + c);
        }
        // W: 32 k x 128 n = 1024 16B-chunks, 8/thread, coalesced
        const float* Wg = W + (size_t)k0 * N + bn * BN;
        #pragma unroll
        for (int t = 0; t < 8; t++) {
            int id = t * 128 + tid;
            int kk = id >> 5;
            int nc = (id & 31) << 2;
            cp16(ws_base + (uint32_t)(((b * BK + kk) * BN + nc) * 4),
                 Wg + (size_t)kk * N + nc);
        }
        cp_commit();
    };

    unsigned long long acc[8][4];   // [m-row][n-pair]
    #pragma unroll
    for (int i = 0; i < 8; i++)
        #pragma unroll
        for (int j = 0; j < 4; j++) acc[i][j] = 0ull;

    load_tiles(0, 0);

    int buf = 0;
    for (int it = 0; it < T; it++) {
        if (it + 1 < T) {
            load_tiles(it + 1, buf ^ 1);
            cp_wait<1>();
        } else {
            cp_wait<0>();
        }
        __syncthreads();

        const float (*Ab)[BK] = As[buf];
        const float (*Wb)[BN] = Ws[buf];

        #pragma unroll
        for (int kk4 = 0; kk4 < BK; kk4 += 4) {
            float4 av[8];
            #pragma unroll
            for (int i = 0; i < 8; i++)
                av[i] = *(const float4*)(&Ab[ty * 8 + i][kk4]);

            #pragma unroll
            for (int j = 0; j < 4; j++) {
                const ulonglong2* wp = (const ulonglong2*)(&Wb[kk4 + j][tx * 8]);
                ulonglong2 wA = wp[0];
                ulonglong2 wB = wp[1];
                #pragma unroll
                for (int i = 0; i < 8; i++) {
                    float a = (j == 0) ? av[i].x : (j == 1) ? av[i].y
                            : (j == 2) ? av[i].z : av[i].w;
                    unsigned long long ad = pack_dup(a);
                    fma2(acc[i][0], ad, wA.x);
                    fma2(acc[i][1], ad, wA.y);
                    fma2(acc[i][2], ad, wB.x);
                    fma2(acc[i][3], ad, wB.y);
                }
            }
        }
        __syncthreads();     // protect buf before it's refilled two iters later
        buf ^= 1;
    }

    // write raw partials: part[sz][row][col]; acc pairs are (n, n+1)
    float* pout = part + (size_t)sz * M * N;
    const int col0 = bn * BN + tx * 8;
    #pragma unroll
    for (int i = 0; i < 8; i++) {
        int row = bm * BM + ty * 8 + i;
        float2 p0 = unpack2(acc[i][0]);
        float2 p1 = unpack2(acc[i][1]);
        float2 p2 = unpack2(acc[i][2]);
        float2 p3 = unpack2(acc[i][3]);
        *(float4*)(pout + (size_t)row * N + col0)     = make_float4(p0.x, p0.y, p1.x, p1.y);
        *(float4*)(pout + (size_t)row * N + col0 + 4) = make_float4(p2.x, p2.y, p3.x, p3.y);
    }
}

// ---------------- reduce 1: h1 = relu(sum_s part1 + b1) --------------------
__global__ void reduce1_kernel(const float* __restrict__ b1) {
    int idx4 = blockIdx.x * blockDim.x + threadIdx.x;        // over (BB*HGN)/4
    if (idx4 >= BB * HGN / 4) return;
    int idx = idx4 * 4;
    int n   = idx % HGN;
    float4 s = *(const float4*)(part1 + idx);
    #pragma unroll
    for (int z = 1; z < S1; z++) {
        float4 v = *(const float4*)(part1 + (size_t)z * BB * HGN + idx);
        s.x += v.x; s.y += v.y; s.z += v.z; s.w += v.w;
    }
    float4 bv = *(const float4*)(b1 + n);
    s.x = fmaxf(s.x + bv.x, 0.0f);
    s.y = fmaxf(s.y + bv.y, 0.0f);
    s.z = fmaxf(s.z + bv.z, 0.0f);
    s.w = fmaxf(s.w + bv.w, 0.0f);
    *(float4*)(h1_buf + idx) = s;
}

// ---------------- final reduce: out = relu(Σpart2+b3) + relu(Σpart3+b4) ----
__global__ void final_reduce_kernel(const float* __restrict__ b3,
                                    const float* __restrict__ b4,
                                    float* __restrict__ out) {
    int idx4 = blockIdx.x * blockDim.x + threadIdx.x;        // over (BB*HOUT)/4
    if (idx4 >= BB * HOUT / 4) return;
    int idx = idx4 * 4;
    int n   = idx % HOUT;

    float4 sg = *(const float4*)(part2 + idx);
    #pragma unroll
    for (int z = 1; z < S2; z++) {
        float4 v = *(const float4*)(part2 + (size_t)z * BB * HOUT + idx);
        sg.x += v.x; sg.y += v.y; sg.z += v.z; sg.w += v.w;
    }
    float4 sl = *(const float4*)(part3 + idx);
    #pragma unroll
    for (int z = 1; z < S3; z++) {
        float4 v = *(const float4*)(part3 + (size_t)z * BB * HOUT + idx);
        sl.x += v.x; sl.y += v.y; sl.z += v.z; sl.w += v.w;
    }
    float4 g3 = *(const float4*)(b3 + n);
    float4 g4 = *(const float4*)(b4 + n);
    float4 o;
    o.x = fmaxf(sg.x + g3.x, 0.0f) + fmaxf(sl.x + g4.x, 0.0f);
    o.y = fmaxf(sg.y + g3.y, 0.0f) + fmaxf(sl.y + g4.y, 0.0f);
    o.z = fmaxf(sg.z + g3.z, 0.0f) + fmaxf(sl.z + g4.z, 0.0f);
    o.w = fmaxf(sg.w + g3.w, 0.0f) + fmaxf(sl.w + g4.w, 0.0f);
    *(float4*)(out + idx) = o;        // relu(hg+hl) == relu(hg)+relu(hl)
}

// ---------------- launch ----------------------------------------------------
extern "C" void kernel_launch(void* const* d_in, const int* in_sizes, int n_in,
                              void* d_out, int out_size) {
    const float* images    = (const float*)d_in[0];
    const float* locations = (const float*)d_in[1];
    const float* W1        = (const float*)d_in[2];
    const float* b1        = (const float*)d_in[3];
    const float* W2        = (const float*)d_in[4];
    const float* b2        = (const float*)d_in[5];
    const float* W3        = (const float*)d_in[6];
    const float* b3        = (const float*)d_in[7];
    const float* W4        = (const float*)d_in[8];
    const float* b4        = (const float*)d_in[9];
    float* out = (float*)d_out;
    (void)in_sizes; (void)n_in; (void)out_size;

    void *gp, *h1p, *h2p, *p1p, *p2p, *p3p;
    cudaGetSymbolAddress(&gp,  g_buf);
    cudaGetSymbolAddress(&h1p, h1_buf);
    cudaGetSymbolAddress(&h2p, h2_buf);
    cudaGetSymbolAddress(&p1p, part1);
    cudaGetSymbolAddress(&p2p, part2);
    cudaGetSymbolAddress(&p3p, part3);

    // 1) foveation -> g_buf
    foveate_kernel<<<(BB * GDIM + 255) / 256, 256>>>(images, locations);

    // 2) location FC -> h2_buf
    loc_fc_kernel<<<BB, HLN>>>(locations, W2, b2);

    // 3) hl partials: h2 @ W4   (256 x 1280, K=256, S=2) -> part3
    gemm_splitk_kernel<<<dim3(HOUT / BN, BB / BM, S3), 128>>>(
        (const float*)h2p, W4, (float*)p3p, BB, HOUT, HLN, HLN / S3);

    // 4) GEMM1 partials: g @ W1 (256 x 1024, K=9216, S=16) -> part1
    gemm_splitk_kernel<<<dim3(HGN / BN, BB / BM, S1), 128>>>(
        (const float*)gp, W1, (float*)p1p, BB, HGN, GDIM, GDIM / S1);

    // 5) h1 = relu(sum part1 + b1)
    reduce1_kernel<<<(BB * HGN / 4 + 255) / 256, 256>>>(b1);

    // 6) out partials: h1 @ W3  (256 x 1280, K=1024, S=8) -> part2
    gemm_splitk_kernel<<<dim3(HOUT / BN, BB / BM, S2), 128>>>(
        (const float*)h1p, W3, (float*)p2p, BB, HOUT, HGN, HGN / S2);

    // 7) out = relu(sum part2 + b3) + relu(sum part3 + b4)
    final_reduce_kernel<<<(BB * HOUT / 4 + 255) / 256, 256>>>(b3, b4, out);
}